// round 4
// baseline (speedup 1.0000x reference)
#include <cuda_runtime.h>
#include <math.h>

#define NPTS 1024
#define TLEN 64
#define CDIM 256
#define NTILE 16                         // 1024 / 64
#define NBLK (NTILE * (NTILE + 1) / 2)   // 136 triangular tiles

typedef unsigned long long ull;

// Scratch (__device__ globals — no allocation allowed).
__device__ float  g_xm[2][NPTS * CDIM];  // time-means (x, y)
__device__ float  g_norm[2][NPTS];       // row squared norms
__device__ float  g_rs[2][NPTS];         // row sums of d (atomic-accumulated)
__device__ double g_acc[3];              // sum(dx*dy), sum(dx*dx), sum(dy*dy)

// ---- packed f32x2 helpers (FFMA2 — ptxas won't emit from C++) ----
__device__ __forceinline__ void ffma2(ull& c, ull a, ull b) {
    asm("fma.rn.f32x2 %0, %1, %2, %0;" : "+l"(c) : "l"(a), "l"(b));
}
__device__ __forceinline__ ull dup2(float v) {
    ull r;
    asm("mov.b64 %0, {%1, %1};" : "=l"(r) : "f"(v));
    return r;
}
__device__ __forceinline__ float2 unpack2(ull v) {
    float2 r;
    asm("mov.b64 {%0, %1}, %2;" : "=f"(r.x), "=f"(r.y) : "l"(v));
    return r;
}

// ---------------------------------------------------------------------------
// Kernel 1: time-mean over T + per-row squared norm.
// grid (512, 2), block 256: each block = 2 rows, 128 threads/row (T split in
// two halves of 32). 262k threads -> ~55 warps/SM for max memory parallelism.
// Streaming loads (__ldcs): inputs are single-use, keep L2 for g_xm.
// ---------------------------------------------------------------------------
__global__ void mean_norm_kernel(const float* __restrict__ a,
                                 const float* __restrict__ b) {
    const int w = blockIdx.y;
    const float* __restrict__ src = (w == 0) ? a : b;
    const int tid  = threadIdx.x;
    const int row  = tid >> 7;           // 0..1 within block
    const int half = (tid >> 6) & 1;     // which 32 timesteps
    const int c4   = tid & 63;           // float4 slot
    const int n    = blockIdx.x * 2 + row;

    if (blockIdx.x == 0) {   // fold init
#pragma unroll
        for (int r = 0; r < 4; ++r) g_rs[w][tid + 256 * r] = 0.f;
        if (w == 0 && tid == 0) { g_acc[0] = 0.0; g_acc[1] = 0.0; g_acc[2] = 0.0; }
    }

    const float4* __restrict__ p =
        (const float4*)(src + (size_t)n * (TLEN * CDIM)) + half * 32 * (CDIM / 4) + c4;
    float4 s = make_float4(0.f, 0.f, 0.f, 0.f);
#pragma unroll
    for (int t = 0; t < 32; ++t) {
        float4 v = __ldcs(p + (size_t)t * (CDIM / 4));
        s.x += v.x; s.y += v.y; s.z += v.z; s.w += v.w;
    }

    __shared__ float4 sh[2][2][64];
    __shared__ float part[2][2];
    sh[row][half][c4] = s;
    __syncthreads();

    if (half == 0) {
        const float4 o = sh[row][1][c4];
        const float inv = 1.0f / TLEN;
        float4 m;
        m.x = (s.x + o.x) * inv; m.y = (s.y + o.y) * inv;
        m.z = (s.z + o.z) * inv; m.w = (s.w + o.w) * inv;
        ((float4*)(g_xm[w] + (size_t)n * CDIM))[c4] = m;

        float sq = m.x * m.x + m.y * m.y + m.z * m.z + m.w * m.w;
#pragma unroll
        for (int off = 16; off > 0; off >>= 1)
            sq += __shfl_down_sync(0xffffffffu, sq, off);
        if ((c4 & 31) == 0) part[row][c4 >> 5] = sq;
    }
    __syncthreads();
    if ((tid & 127) == 0) g_norm[w][n] = part[row][0] + part[row][1];
}

// ---------------------------------------------------------------------------
// Kernel 2: triangular pairwise-distance GEMM, fully fused statistics.
// 64x64 tile, 256 threads (2 warps/SMSP), 4x4 micro-tile, f32x2 FMAs, both
// matrices per block; d never materialized. grid 136 = one wave.
// ---------------------------------------------------------------------------
__global__ void __launch_bounds__(256) gemm_dist_fused_kernel() {
    const int t = blockIdx.x;
    int by = (int)((__fsqrt_rn(8.f * (float)t + 1.f) - 1.f) * 0.5f);
    while ((by + 1) * (by + 2) / 2 <= t) ++by;
    while (by * (by + 1) / 2 > t) --by;
    const int bx = t - by * (by + 1) / 2;
    const bool diag = (bx == by);
    const int I = bx * 64;   // rows
    const int J = by * 64;   // cols

    const float* __restrict__ Xx = g_xm[0];
    const float* __restrict__ Xy = g_xm[1];

    __shared__ __align__(16) float Ax[32][68], Ay[32][68];
    __shared__ __align__(16) float Bx[32][68], By[32][68];
    __shared__ float sh_rsx[64], sh_rsy[64];
    __shared__ float sh_csx[64], sh_csy[64];
    __shared__ float sh_p[3][8];

    const int tid = threadIdx.x;    // 0..255
    const int tx = tid & 15;        // j group (4 cols)
    const int ty = tid >> 4;        // i group (4 rows, 0..15)

    if (tid < 64) { sh_csx[tid] = 0.f; sh_csy[tid] = 0.f; }

    ull accx[2][4], accy[2][4];     // [i-pair][j]
#pragma unroll
    for (int ip = 0; ip < 2; ++ip)
#pragma unroll
        for (int j = 0; j < 4; ++j) { accx[ip][j] = 0ull; accy[ip][j] = 0ull; }

    const int mm = tid >> 3;            // 0..31 base row
    const int kk = (tid & 7) * 4;       // k offset 0..28

    float4 vax[2], vay[2], vbx[2], vby[2];
#pragma unroll
    for (int r = 0; r < 2; ++r) {
        const int m = mm + 32 * r;
        vax[r] = *(const float4*)(Xx + (size_t)(I + m) * CDIM + kk);
        vay[r] = *(const float4*)(Xy + (size_t)(I + m) * CDIM + kk);
        vbx[r] = *(const float4*)(Xx + (size_t)(J + m) * CDIM + kk);
        vby[r] = *(const float4*)(Xy + (size_t)(J + m) * CDIM + kk);
    }

    for (int c = 0; c < 8; ++c) {
        __syncthreads();
#pragma unroll
        for (int r = 0; r < 2; ++r) {
            const int m = mm + 32 * r;
            Ax[kk + 0][m] = vax[r].x; Ax[kk + 1][m] = vax[r].y;
            Ax[kk + 2][m] = vax[r].z; Ax[kk + 3][m] = vax[r].w;
            Ay[kk + 0][m] = vay[r].x; Ay[kk + 1][m] = vay[r].y;
            Ay[kk + 2][m] = vay[r].z; Ay[kk + 3][m] = vay[r].w;
            Bx[kk + 0][m] = vbx[r].x; Bx[kk + 1][m] = vbx[r].y;
            Bx[kk + 2][m] = vbx[r].z; Bx[kk + 3][m] = vbx[r].w;
            By[kk + 0][m] = vby[r].x; By[kk + 1][m] = vby[r].y;
            By[kk + 2][m] = vby[r].z; By[kk + 3][m] = vby[r].w;
        }
        __syncthreads();
        if (c < 7) {
            const int k0 = (c + 1) * 32;
#pragma unroll
            for (int r = 0; r < 2; ++r) {
                const int m = mm + 32 * r;
                vax[r] = *(const float4*)(Xx + (size_t)(I + m) * CDIM + k0 + kk);
                vay[r] = *(const float4*)(Xy + (size_t)(I + m) * CDIM + k0 + kk);
                vbx[r] = *(const float4*)(Xx + (size_t)(J + m) * CDIM + k0 + kk);
                vby[r] = *(const float4*)(Xy + (size_t)(J + m) * CDIM + k0 + kk);
            }
        }
#pragma unroll
        for (int k = 0; k < 32; ++k) {
            {
                ulonglong2 a2 = *(const ulonglong2*)&Ax[k][ty * 4];
                float4 b4 = *(const float4*)&Bx[k][tx * 4];
                const ull ap[2] = {a2.x, a2.y};
                const ull bd[4] = {dup2(b4.x), dup2(b4.y), dup2(b4.z), dup2(b4.w)};
#pragma unroll
                for (int ip = 0; ip < 2; ++ip)
#pragma unroll
                    for (int j = 0; j < 4; ++j)
                        ffma2(accx[ip][j], ap[ip], bd[j]);
            }
            {
                ulonglong2 a2 = *(const ulonglong2*)&Ay[k][ty * 4];
                float4 b4 = *(const float4*)&By[k][tx * 4];
                const ull ap[2] = {a2.x, a2.y};
                const ull bd[4] = {dup2(b4.x), dup2(b4.y), dup2(b4.z), dup2(b4.w)};
#pragma unroll
                for (int ip = 0; ip < 2; ++ip)
#pragma unroll
                    for (int j = 0; j < 4; ++j)
                        ffma2(accy[ip][j], ap[ip], bd[j]);
            }
        }
    }

    // -------- Epilogue: distances in registers, fused statistics --------
    float nIx[4], nIy[4], nJx[4], nJy[4];
#pragma unroll
    for (int i = 0; i < 4; ++i) {
        nIx[i] = g_norm[0][I + ty * 4 + i];
        nIy[i] = g_norm[1][I + ty * 4 + i];
    }
#pragma unroll
    for (int j = 0; j < 4; ++j) {
        nJx[j] = g_norm[0][J + tx * 4 + j];
        nJy[j] = g_norm[1][J + tx * 4 + j];
    }

    float pxy = 0.f, pxx = 0.f, pyy = 0.f;
    float rowx[4], rowy[4], colx[4] = {0, 0, 0, 0}, coly[4] = {0, 0, 0, 0};

#pragma unroll
    for (int ip = 0; ip < 2; ++ip) {
        float2 cx[4], cy[4];
#pragma unroll
        for (int j = 0; j < 4; ++j) { cx[j] = unpack2(accx[ip][j]); cy[j] = unpack2(accy[ip][j]); }
#pragma unroll
        for (int h = 0; h < 2; ++h) {
            const int i = 2 * ip + h;
            float rx = 0.f, ry = 0.f;
#pragma unroll
            for (int j = 0; j < 4; ++j) {
                const float gx = h ? cx[j].y : cx[j].x;
                const float gy = h ? cy[j].y : cy[j].x;
                const float dx = sqrtf(fmaxf(nIx[i] + nJx[j] - 2.f * gx, 0.f) + 1e-12f);
                const float dy = sqrtf(fmaxf(nIy[i] + nJy[j] - 2.f * gy, 0.f) + 1e-12f);
                pxy = fmaf(dx, dy, pxy);
                pxx = fmaf(dx, dx, pxx);
                pyy = fmaf(dy, dy, pyy);
                rx += dx; ry += dy;
                colx[j] += dx; coly[j] += dy;
            }
            rowx[i] = rx; rowy[i] = ry;
        }
    }

    // row sums: reduce across tx (16 lanes within half-warp share ty)
#pragma unroll
    for (int i = 0; i < 4; ++i) {
        float rx = rowx[i], ry = rowy[i];
#pragma unroll
        for (int off = 8; off > 0; off >>= 1) {
            rx += __shfl_down_sync(0xffffffffu, rx, off, 16);
            ry += __shfl_down_sync(0xffffffffu, ry, off, 16);
        }
        if (tx == 0) { sh_rsx[ty * 4 + i] = rx; sh_rsy[ty * 4 + i] = ry; }
    }
    __syncthreads();
    // col sums: shared atomics (16 ty groups, 2-way conflicts max)
#pragma unroll
    for (int j = 0; j < 4; ++j) {
        atomicAdd(&sh_csx[tx * 4 + j], colx[j]);
        atomicAdd(&sh_csy[tx * 4 + j], coly[j]);
    }

    // scalar products: block reduce over 8 warps
#pragma unroll
    for (int off = 16; off > 0; off >>= 1) {
        pxy += __shfl_down_sync(0xffffffffu, pxy, off);
        pxx += __shfl_down_sync(0xffffffffu, pxx, off);
        pyy += __shfl_down_sync(0xffffffffu, pyy, off);
    }
    if ((tid & 31) == 0) {
        sh_p[0][tid >> 5] = pxy; sh_p[1][tid >> 5] = pxx; sh_p[2][tid >> 5] = pyy;
    }
    __syncthreads();

    if (tid < 64) {
        atomicAdd(&g_rs[0][I + tid], sh_rsx[tid]);
        atomicAdd(&g_rs[1][I + tid], sh_rsy[tid]);
        if (!diag) {   // symmetric contribution to rows J..
            atomicAdd(&g_rs[0][J + tid], sh_csx[tid]);
            atomicAdd(&g_rs[1][J + tid], sh_csy[tid]);
        }
    }
    if (tid == 0) {
        const double scl = diag ? 1.0 : 2.0;
        double s0 = 0, s1 = 0, s2 = 0;
#pragma unroll
        for (int q = 0; q < 8; ++q) { s0 += sh_p[0][q]; s1 += sh_p[1][q]; s2 += sh_p[2][q]; }
        atomicAdd(&g_acc[0], scl * s0);
        atomicAdd(&g_acc[1], scl * s1);
        atomicAdd(&g_acc[2], scl * s2);
    }
}

// ---------------------------------------------------------------------------
// Kernel 3: finalize via the double-centering identity (double precision):
//  sum(a*b) = S_xy - (2/N) * sum_i Rx_i*Ry_i + Tx*Ty/N^2
// ---------------------------------------------------------------------------
__global__ void finalize_kernel(float* __restrict__ out) {
    const int t = threadIdx.x;   // 512 threads, 2 rows each
    double sRR = 0.0, sXX = 0.0, sYY = 0.0, sX = 0.0, sY = 0.0;
#pragma unroll
    for (int q = 0; q < 2; ++q) {
        const int i = t + q * 512;
        const double rx = (double)g_rs[0][i];
        const double ry = (double)g_rs[1][i];
        sRR += rx * ry; sXX += rx * rx; sYY += ry * ry; sX += rx; sY += ry;
    }
#pragma unroll
    for (int off = 16; off > 0; off >>= 1) {
        sRR += __shfl_down_sync(0xffffffffu, sRR, off);
        sXX += __shfl_down_sync(0xffffffffu, sXX, off);
        sYY += __shfl_down_sync(0xffffffffu, sYY, off);
        sX  += __shfl_down_sync(0xffffffffu, sX, off);
        sY  += __shfl_down_sync(0xffffffffu, sY, off);
    }
    __shared__ double sd[5][16];
    const int lane = t & 31, wid = t >> 5;
    if (lane == 0) { sd[0][wid] = sRR; sd[1][wid] = sXX; sd[2][wid] = sYY; sd[3][wid] = sX; sd[4][wid] = sY; }
    __syncthreads();
    if (t == 0) {
        double a0 = 0, a1 = 0, a2 = 0, a3 = 0, a4 = 0;
#pragma unroll
        for (int q = 0; q < 16; ++q) {
            a0 += sd[0][q]; a1 += sd[1][q]; a2 += sd[2][q]; a3 += sd[3][q]; a4 += sd[4][q];
        }
        const double N = (double)NPTS, N2 = N * N;
        const double sumab = g_acc[0] - (2.0 / N) * a0 + (a3 * a4) / N2;
        const double sumaa = g_acc[1] - (2.0 / N) * a1 + (a3 * a3) / N2;
        const double sumbb = g_acc[2] - (2.0 / N) * a2 + (a4 * a4) / N2;
        const double mxy = sumab / N2, mxx = sumaa / N2, myy = sumbb / N2;
        const double r = mxy / sqrt(mxx * myy + 1e-9);
        out[0] = (float)(1.0 - r);
    }
}

extern "C" void kernel_launch(void* const* d_in, const int* in_sizes, int n_in,
                              void* d_out, int out_size) {
    const float* a = (const float*)d_in[0];  // output_1 (1024,64,256) f32
    const float* b = (const float*)d_in[1];  // feature  (1024,64,256) f32
    // d_in[2] = mask, unused by the reference module.

    mean_norm_kernel<<<dim3(NPTS / 2, 2), 256>>>(a, b);
    gemm_dist_fused_kernel<<<NBLK, 256>>>();
    finalize_kernel<<<1, 512>>>((float*)d_out);
}